// round 16
// baseline (speedup 1.0000x reference)
#include <cuda_runtime.h>
#include <cuda_fp16.h>
#include <cuda.h>
#include <cstdint>

#define BB 8
#define NN 4096
#define FI 128
#define FO 64
#define BI 128
#define BJ 64
#define NT (NN / BJ)
#define PPITCH 72

// k_attn shared memory layout (dynamic) — R13 verbatim:
#define ASTAGE_B 32768
#define HSTAGE_B 8192
#define ADJ_OFF  0
#define H_OFF    (2 * ASTAGE_B)             // 65536
#define P_OFF    (H_OFF + 2 * HSTAGE_B)     // 81920
#define RS_OFF   (P_OFF + BI * PPITCH * 2)  // 100352
#define BAR_OFF  (RS_OFF + BI * 4)          // 100864
#define ATTN_SMEM (BAR_OFF + 32)            // 100896

// Scratch (static __device__ — no allocation allowed)
// h_fp16: per batch, tile-major; within 64-row tile: row lr, byte col cb at
// lr*128 + (cb ^ ((lr&7)<<4))  (SW128 pre-swizzle).
__device__ __align__(1024) __half h_fp16[(size_t)BB * NN * FO];   // 4 MB
__device__ float  s1_g[BB * NN];
__device__ float  s2_g[BB * NN];
__device__ float2 pq1_g[BB * NN];                 // {P1, Q1} per (b,i)
__device__ float2 pq2_g[BB * NN];                 // {P2, Q2} per (b,j)
__device__ float2 w12_g[FI];                      // {W@a1, W@a2} per f

// ---------------------------------------------------------------------------
// PTX helpers
// ---------------------------------------------------------------------------
__device__ __forceinline__ void ldsm4(uint32_t& r0, uint32_t& r1, uint32_t& r2, uint32_t& r3, uint32_t addr)
{
    asm volatile("ldmatrix.sync.aligned.m8n8.x4.shared.b16 {%0,%1,%2,%3}, [%4];"
                 : "=r"(r0), "=r"(r1), "=r"(r2), "=r"(r3) : "r"(addr));
}
__device__ __forceinline__ void ldsm4t(uint32_t& r0, uint32_t& r1, uint32_t& r2, uint32_t& r3, uint32_t addr)
{
    asm volatile("ldmatrix.sync.aligned.m8n8.x4.trans.shared.b16 {%0,%1,%2,%3}, [%4];"
                 : "=r"(r0), "=r"(r1), "=r"(r2), "=r"(r3) : "r"(addr));
}
__device__ __forceinline__ void mma16816(float* d, uint32_t a0, uint32_t a1, uint32_t a2, uint32_t a3,
                                         uint32_t b0, uint32_t b1)
{
    asm volatile("mma.sync.aligned.m16n8k16.row.col.f32.f16.f16.f32 "
                 "{%0,%1,%2,%3}, {%4,%5,%6,%7}, {%8,%9}, {%0,%1,%2,%3};"
                 : "+f"(d[0]), "+f"(d[1]), "+f"(d[2]), "+f"(d[3])
                 : "r"(a0), "r"(a1), "r"(a2), "r"(a3), "r"(b0), "r"(b1));
}
__device__ __forceinline__ void bulk_g2s(uint32_t dst, const void* src, uint32_t bytes, uint32_t bar)
{
    asm volatile("cp.async.bulk.shared::cluster.global.mbarrier::complete_tx::bytes "
                 "[%0], [%1], %2, [%3];"
                 :: "r"(dst), "l"(src), "r"(bytes), "r"(bar) : "memory");
}
__device__ __forceinline__ void tma3d(uint32_t dst, const CUtensorMap* map,
                                      int cx_, int cy_, int cz_, uint32_t bar)
{
    asm volatile("cp.async.bulk.tensor.3d.shared::cta.global.tile.mbarrier::complete_tx::bytes "
                 "[%0], [%1, {%2, %3, %4}], [%5];"
                 :: "r"(dst), "l"(map), "r"(cx_), "r"(cy_), "r"(cz_), "r"(bar) : "memory");
}
#define MBINIT(addr, cnt) \
    asm volatile("mbarrier.init.shared.b64 [%0], %1;" :: "r"(addr), "r"(cnt) : "memory")
#define MBARR(addr) \
    asm volatile("mbarrier.arrive.release.cta.shared.b64 _, [%0];" :: "r"(addr) : "memory")
#define MBEXP(addr, tx) \
    asm volatile("mbarrier.arrive.expect_tx.shared.b64 _, [%0], %1;" :: "r"(addr), "r"((uint32_t)(tx)) : "memory")
#define MBWAIT(addr, ph) do {                                                       \
    uint32_t _m = (addr); uint32_t _p = (ph); uint32_t _ok;                         \
    asm volatile("{\n\t.reg .pred p;\n\t"                                           \
        "mbarrier.try_wait.parity.acquire.cta.shared::cta.b64 p, [%1], %2;\n\t"     \
        "selp.b32 %0, 1, 0, p;\n\t}" : "=r"(_ok) : "r"(_m), "r"(_p) : "memory");    \
    if (!_ok) {                                                                     \
        asm volatile("{\n\t.reg .pred P1;\n\t"                                      \
            "WL_%=:\n\t"                                                            \
            "mbarrier.try_wait.parity.acquire.cta.shared::cta.b64 P1, [%0], %1, 0x989680;\n\t" \
            "@P1 bra.uni WD_%=;\n\t"                                                \
            "bra.uni WL_%=;\n\t"                                                    \
            "WD_%=:\n\t}" :: "r"(_m), "r"(_p) : "memory");                          \
    }                                                                               \
} while (0)
#define PAIRBAR(id) \
    asm volatile("bar.sync %0, 64;" :: "r"(id) : "memory")

// ---------------------------------------------------------------------------
// Kernel A0: w12 = W @ [a1, a2]  (128 threads, one block)
// ---------------------------------------------------------------------------
__global__ void k_wa(const float* __restrict__ W, const float* __restrict__ a)
{
    const int f = threadIdx.x;    // 0..127
    float s1 = 0.f, s2 = 0.f;
#pragma unroll 8
    for (int o = 0; o < FO; o++) {
        float w = W[f * FO + o];
        s1 += w * a[o];
        s2 += w * a[FO + o];
    }
    w12_g[f] = make_float2(s1, s2);
}

// ---------------------------------------------------------------------------
// Kernel A1 (tensor cores): h = inp @ W via fp16 mma.sync (fp32 accum),
// stored SW128 tile-major fp16. s1/s2 = inp @ w12 in EXACT fp32 during load.
// 512 CTAs x 128 threads (4 warps); warp w: rows w*16..+15, all 64 cols.
// ---------------------------------------------------------------------------
#define IPITCH 136   // halves per inp_sm row (272B: 16B-aligned, conflict-free)
#define WPITCH 72    // halves per W_sm row (144B, same as k_attn h)

__global__ __launch_bounds__(128) void k_h(const float* __restrict__ inp,
                                           const float* __restrict__ W)
{
    __shared__ __align__(16) __half inp_sm[64 * IPITCH];   // 17.4 KB
    __shared__ __align__(16) __half W_sm[FI * WPITCH];     // 18.4 KB
    __shared__ float2 w12_sm[FI];                          // 1 KB

    const int tid  = threadIdx.x;
    const int lane = tid & 31;
    const int warp = tid >> 5;
    const int blk  = blockIdx.x;                 // 0 .. BB*NN/64-1
    const int b    = blk / (NN / 64);
    const int i0   = (blk % (NN / 64)) * 64;

    // w12 table
    if (tid < FI) w12_sm[tid] = __ldg(&w12_g[tid]);

    // W -> fp16 SMEM: thread f handles W row f (64 floats = 16 float4)
    {
        const float4* Wr = (const float4*)(W + tid * FO);
        __half* dst = W_sm + tid * WPITCH;
#pragma unroll
        for (int k = 0; k < 16; k++) {
            float4 v = __ldg(&Wr[k]);
            ((__half2*)dst)[2 * k]     = __floats2half2_rn(v.x, v.y);
            ((__half2*)dst)[2 * k + 1] = __floats2half2_rn(v.z, v.w);
        }
    }
    __syncthreads();   // w12_sm ready (W_sm also synced again below)

    // inp: thread t handles row t>>1, segment (t&1)*64 (64 floats).
    // fp32 dot with w12 BEFORE fp16 conversion -> exact s1/s2.
    {
        const int row = tid >> 1;
        const int seg = (tid & 1) * 64;
        const float4* ir = (const float4*)(inp + ((size_t)(b * NN + i0 + row)) * FI + seg);
        __half* dst = inp_sm + row * IPITCH + seg;
        float s1p = 0.f, s2p = 0.f;
#pragma unroll
        for (int k = 0; k < 16; k++) {
            float4 v = __ldg(&ir[k]);
            float2 w0 = w12_sm[seg + 4 * k];
            float2 w1 = w12_sm[seg + 4 * k + 1];
            float2 w2 = w12_sm[seg + 4 * k + 2];
            float2 w3 = w12_sm[seg + 4 * k + 3];
            s1p += v.x * w0.x + v.y * w1.x + v.z * w2.x + v.w * w3.x;
            s2p += v.x * w0.y + v.y * w1.y + v.z * w2.y + v.w * w3.y;
            ((__half2*)dst)[2 * k]     = __floats2half2_rn(v.x, v.y);
            ((__half2*)dst)[2 * k + 1] = __floats2half2_rn(v.z, v.w);
        }
        s1p += __shfl_xor_sync(0xffffffffu, s1p, 1);
        s2p += __shfl_xor_sync(0xffffffffu, s2p, 1);
        if ((tid & 1) == 0) {
            s1_g[b * NN + i0 + row] = s1p;
            s2_g[b * NN + i0 + row] = s2p;
        }
    }
    __syncthreads();

    // ---- MMA: h[w*16..+15][0..63] = inp @ W, K=128 (8 ks steps) ----
    const uint32_t sa = (uint32_t)__cvta_generic_to_shared(inp_sm);
    const uint32_t sw = (uint32_t)__cvta_generic_to_shared(W_sm);
    const uint32_t a_base = sa + (uint32_t)(((warp * 16 + (lane & 15)) * IPITCH + (lane >> 4) * 8) * 2);
    const uint32_t b_base = sw + (uint32_t)(((lane & 15) * WPITCH + (lane >> 4) * 8) * 2);

    float acc[8][4];
#pragma unroll
    for (int m = 0; m < 8; m++)
#pragma unroll
        for (int k = 0; k < 4; k++) acc[m][k] = 0.f;

#pragma unroll
    for (int ks = 0; ks < 8; ks++) {
        uint32_t a0, a1, a2, a3;
        ldsm4(a0, a1, a2, a3, a_base + ks * 32);
#pragma unroll
        for (int nt = 0; nt < 4; nt++) {
            uint32_t b0, b1, b2, b3;
            ldsm4t(b0, b1, b2, b3, b_base + (uint32_t)((ks * 16 * WPITCH + nt * 16) * 2));
            mma16816(acc[nt * 2],     a0, a1, a2, a3, b0, b1);
            mma16816(acc[nt * 2 + 1], a0, a1, a2, a3, b2, b3);
        }
    }

    // ---- store h fp16, SW128 tile-major (matches k_attn reader) ----
    char* tile_base = (char*)h_fp16 + ((size_t)b * NN + i0) * (FO * 2);
    const int lr0 = warp * 16 + (lane >> 2);
#pragma unroll
    for (int m = 0; m < 8; m++) {
        const int colb = (m * 8 + (lane & 3) * 2) * 2;   // byte col
        __half2 vlo = __floats2half2_rn(acc[m][0], acc[m][1]);
        __half2 vhi = __floats2half2_rn(acc[m][2], acc[m][3]);
        uint32_t s0 = (uint32_t)(lr0 * 128) + (((uint32_t)colb) ^ (((uint32_t)lr0 & 7u) << 4));
        uint32_t s1v = (uint32_t)((lr0 + 8) * 128) + (((uint32_t)colb) ^ (((uint32_t)(lr0 + 8) & 7u) << 4));
        *reinterpret_cast<__half2*>(tile_base + s0)  = vlo;
        *reinterpret_cast<__half2*>(tile_base + s1v) = vhi;
    }
}

// ---------------------------------------------------------------------------
// Kernel A2: exp factor tables.  exp(lrelu(s1+s2) - M/L) = max(P1*P2, Q1*Q2)
// ---------------------------------------------------------------------------
__global__ void k_pq()
{
    const int b = blockIdx.x;
    const int tid = threadIdx.x;      // 512 threads
    __shared__ float red[16];

    const float* s2b = s2_g + b * NN;
    float mx = -1e30f;
    for (int j = tid; j < NN; j += 512) mx = fmaxf(mx, s2b[j]);
#pragma unroll
    for (int m = 16; m >= 1; m >>= 1)
        mx = fmaxf(mx, __shfl_xor_sync(0xffffffffu, mx, m));
    if ((tid & 31) == 0) red[tid >> 5] = mx;
    __syncthreads();
    if (tid == 0) {
        float v = red[0];
        for (int k = 1; k < 16; k++) v = fmaxf(v, red[k]);
        red[0] = v;
    }
    __syncthreads();

    const float L = 1.4426950408889634f;
    const float s2maxL = red[0] * L;
    for (int j = tid; j < NN; j += 512) {
        float sL = s2b[j] * L;
        pq2_g[b * NN + j] = make_float2(exp2f(sL), exp2f(0.2f * sL));
        float s1L = s1_g[b * NN + j] * L;
        float t = s1L + s2maxL;
        float M = fmaxf(t, 0.2f * t);
        pq1_g[b * NN + j] = make_float2(exp2f(s1L - M), exp2f(0.2f * s1L - M));
    }
}

// ---------------------------------------------------------------------------
// Kernel B (R13 verbatim): fused mask + softmax(no-rescale) + PV matmul + elu.
// 256 CTAs x 256 threads (8 warps), 2 CTAs/SM — single wave. Warp pairs
// decoupled via named barriers; stages recycled via free[] mbarriers.
// ---------------------------------------------------------------------------
__global__ __launch_bounds__(256, 2) void k_attn(
    const __grid_constant__ CUtensorMap tm_adj,
    float* __restrict__ out)
{
    extern __shared__ __align__(1024) unsigned char smem[];
    const uint32_t sb = (uint32_t)__cvta_generic_to_shared(smem);
    __half* p_sm = (__half*)(smem + P_OFF);
    float* rs_sm = (float*)(smem + RS_OFF);

    const int tid  = threadIdx.x;
    const int lane = tid & 31;
    const int warp = tid >> 5;
    const int rg   = warp & 3;
    const int ch   = warp >> 2;
    const int blk  = blockIdx.x;
    const int b    = blk >> 5;
    const int i0   = (blk & 31) * BI;

    const int lane64 = ch * 32 + lane;
    const int cx  = lane64 & 15;
    const int ry2 = lane64 >> 4;

    const uint32_t fullb = sb + BAR_OFF;
    const uint32_t freeb = sb + BAR_OFF + 16;

    if (tid == 0) {
        MBINIT(fullb + 0, 1);
        MBINIT(fullb + 8, 1);
        MBINIT(freeb + 0, 8);
        MBINIT(freeb + 8, 8);
    }
    __syncthreads();

    auto issue = [&](int u) {
        const int s = u & 1;
        const uint32_t bar = fullb + s * 8;
        MBEXP(bar, ASTAGE_B + HSTAGE_B);
        tma3d(sb + ADJ_OFF + s * ASTAGE_B, &tm_adj, u * BJ, i0, b, bar);
        bulk_g2s(sb + H_OFF + s * HSTAGE_B,
                 (const char*)h_fp16 + (size_t)b * NN * (FO * 2) + (size_t)u * HSTAGE_B,
                 HSTAGE_B, bar);
    };

    if (tid == 0) { issue(0); issue(1); }

    float acc[2][4][4];
#pragma unroll
    for (int rt = 0; rt < 2; rt++)
#pragma unroll
        for (int nt = 0; nt < 4; nt++)
#pragma unroll
            for (int k = 0; k < 4; k++) acc[rt][nt][k] = 0.f;

    float P1f[8], Q1f[8], rsl[8];
    {
        const float2* pq1b = pq1_g + b * NN + i0 + rg * 32;
#pragma unroll
        for (int ps = 0; ps < 8; ps++) {
            float2 pq = __ldg(&pq1b[ps * 4 + ry2]);
            P1f[ps] = pq.x; Q1f[ps] = pq.y;
            rsl[ps] = 0.f;
        }
    }

    const float2* pq2b = pq2_g + b * NN;

    const uint32_t a_addr0 = sb + P_OFF
        + (uint32_t)(((rg * 32 + (lane & 15)) * PPITCH + (lane >> 4) * 8) * 2);
    const uint32_t a_addr1 = a_addr0 + (uint32_t)(16 * PPITCH * 2);
    const uint32_t b_base = sb + H_OFF
        + (uint32_t)((lane & 15) * 128)
        + (uint32_t)(((uint32_t)(ch * 64) | (((uint32_t)lane >> 4) << 4)) ^ (((uint32_t)lane & 7u) << 4));

    const int barid = rg + 1;

    for (int t = 0; t < NT; t++) {
        const int s = t & 1;
        const int ph = (t >> 1) & 1;
        MBWAIT(fullb + s * 8, ph);

        const uint32_t astage = sb + ADJ_OFF + s * ASTAGE_B;
        float4 pa = *(const float4*)(pq2b + t * BJ + cx * 4);
        float4 pb = *(const float4*)(pq2b + t * BJ + cx * 4 + 2);
#pragma unroll
        for (int ps = 0; ps < 8; ps++) {
            int row = rg * 32 + ps * 4 + ry2;
            int4 av;
            asm volatile("ld.shared.v4.u32 {%0,%1,%2,%3}, [%4];"
                         : "=r"(av.x), "=r"(av.y), "=r"(av.z), "=r"(av.w)
                         : "r"(astage + (uint32_t)(row * 256 + cx * 16)));
            float p0 = av.x ? fmaxf(P1f[ps] * pa.x, Q1f[ps] * pa.y) : 0.f;
            float p1 = av.y ? fmaxf(P1f[ps] * pa.z, Q1f[ps] * pa.w) : 0.f;
            float p2 = av.z ? fmaxf(P1f[ps] * pb.x, Q1f[ps] * pb.y) : 0.f;
            float p3 = av.w ? fmaxf(P1f[ps] * pb.z, Q1f[ps] * pb.w) : 0.f;
            __half2 q01 = __floats2half2_rn(p0, p1);
            __half2 q23 = __floats2half2_rn(p2, p3);
            float2 lo = __half22float2(q01);
            float2 hi = __half22float2(q23);
            rsl[ps] += (lo.x + lo.y) + (hi.x + hi.y);
            uint2 pk;
            pk.x = reinterpret_cast<uint32_t&>(q01);
            pk.y = reinterpret_cast<uint32_t&>(q23);
            *reinterpret_cast<uint2*>(&p_sm[row * PPITCH + cx * 4]) = pk;
        }

        PAIRBAR(barid);

        const uint32_t hb = b_base + (uint32_t)(s * HSTAGE_B);
#pragma unroll
        for (int ks = 0; ks < 4; ks++) {
            uint32_t a0, a1, a2, a3, a4, a5, a6, a7;
            ldsm4(a0, a1, a2, a3, a_addr0 + ks * 32);
            ldsm4(a4, a5, a6, a7, a_addr1 + ks * 32);
            uint32_t baddr = hb + (uint32_t)(ks * 2048);
            uint32_t b0, b1, b2, b3;
            ldsm4t(b0, b1, b2, b3, baddr);
            mma16816(acc[0][0], a0, a1, a2, a3, b0, b1);
            mma16816(acc[0][1], a0, a1, a2, a3, b2, b3);
            mma16816(acc[1][0], a4, a5, a6, a7, b0, b1);
            mma16816(acc[1][1], a4, a5, a6, a7, b2, b3);
            uint32_t c0, c1, c2, c3;
            ldsm4t(c0, c1, c2, c3, baddr ^ 32u);
            mma16816(acc[0][2], a0, a1, a2, a3, c0, c1);
            mma16816(acc[0][3], a0, a1, a2, a3, c2, c3);
            mma16816(acc[1][2], a4, a5, a6, a7, c0, c1);
            mma16816(acc[1][3], a4, a5, a6, a7, c2, c3);
        }

        if (lane == 0) MBARR(freeb + s * 8);

        if (tid == 0 && t + 2 < NT) {
            MBWAIT(freeb + s * 8, ph);
            issue(t + 2);
        }

        PAIRBAR(barid);
    }

#pragma unroll
    for (int ps = 0; ps < 8; ps++) {
        float v = rsl[ps];
#pragma unroll
        for (int m = 8; m >= 1; m >>= 1)
            v += __shfl_xor_sync(0xffffffffu, v, m);
        if (cx == 0) rs_sm[rg * 32 + ps * 4 + ry2] = v;
    }
    __syncthreads();

    float* ob = out + (size_t)b * NN * FO;
#pragma unroll
    for (int rt = 0; rt < 2; rt++) {
        const int r_loc = rg * 32 + rt * 16 + (lane >> 2);
        const float inv_lo = 1.f / rs_sm[r_loc];
        const float inv_hi = 1.f / rs_sm[r_loc + 8];
#pragma unroll
        for (int nt = 0; nt < 4; nt++) {
            int col = ch * 32 + nt * 8 + (lane & 3) * 2;
            float v0 = acc[rt][nt][0] * inv_lo;
            float v1 = acc[rt][nt][1] * inv_lo;
            float v2 = acc[rt][nt][2] * inv_hi;
            float v3 = acc[rt][nt][3] * inv_hi;
            v0 = v0 > 0.f ? v0 : expm1f(v0);
            v1 = v1 > 0.f ? v1 : expm1f(v1);
            v2 = v2 > 0.f ? v2 : expm1f(v2);
            v3 = v3 > 0.f ? v3 : expm1f(v3);
            *reinterpret_cast<float2*>(&ob[(size_t)(i0 + r_loc) * FO + col])     = make_float2(v0, v1);
            *reinterpret_cast<float2*>(&ob[(size_t)(i0 + r_loc + 8) * FO + col]) = make_float2(v2, v3);
        }
    }
}

// ---------------------------------------------------------------------------
extern "C" void kernel_launch(void* const* d_in, const int* in_sizes, int n_in,
                              void* d_out, int out_size)
{
    const float* inp = (const float*)d_in[0];
    const int*   adj = (const int*)d_in[1];
    const float* W   = (const float*)d_in[2];
    const float* a   = (const float*)d_in[3];
    float* out = (float*)d_out;

    cudaFuncSetAttribute(k_attn, cudaFuncAttributeMaxDynamicSharedMemorySize, ATTN_SMEM);

    typedef CUresult (*EncodeFn)(CUtensorMap*, CUtensorMapDataType, cuuint32_t, void*,
                                 const cuuint64_t*, const cuuint64_t*, const cuuint32_t*,
                                 const cuuint32_t*, CUtensorMapInterleave, CUtensorMapSwizzle,
                                 CUtensorMapL2promotion, CUtensorMapFloatOOBfill);
    EncodeFn encode = nullptr;
    {
        void* fn = nullptr;
        cudaDriverEntryPointQueryResult q;
        cudaGetDriverEntryPointByVersion("cuTensorMapEncodeTiled", &fn, 12030,
                                         cudaEnableDefault, &q);
        encode = (EncodeFn)fn;
    }

    // adj: (x=j 4096, y=i 4096, z=b 8), box (64, 128, 1), no swizzle (256B rows)
    CUtensorMap tm_adj;
    {
        cuuint64_t dims[3]    = {(cuuint64_t)NN, (cuuint64_t)NN, (cuuint64_t)BB};
        cuuint64_t strides[2] = {(cuuint64_t)NN * 4, (cuuint64_t)NN * NN * 4};
        cuuint32_t box[3]     = {BJ, BI, 1};
        cuuint32_t estr[3]    = {1, 1, 1};
        encode(&tm_adj, CU_TENSOR_MAP_DATA_TYPE_UINT32, 3, (void*)adj,
               dims, strides, box, estr,
               CU_TENSOR_MAP_INTERLEAVE_NONE, CU_TENSOR_MAP_SWIZZLE_NONE,
               CU_TENSOR_MAP_L2_PROMOTION_L2_128B, CU_TENSOR_MAP_FLOAT_OOB_FILL_NONE);
    }

    k_wa<<<1, 128>>>(W, a);
    k_h<<<BB * NN / 64, 128>>>(inp, W);
    k_pq<<<BB, 512>>>();
    k_attn<<<BB * (NN / BI), 256, ATTN_SMEM>>>(tm_adj, out);
}